// round 17
// baseline (speedup 1.0000x reference)
#include <cuda_runtime.h>
#include <cuda_fp16.h>
#include <cstdint>

// ============================================================================
// Y[500000,256] = X @ W via mma.sync f16 m16n8k16 (f32 accum).
// R16: occupancy push. Quarter-N CTAs: 128 rows x 64 cols, B 32KB,
// K_CHUNK=32 (A 2x8KB) => 48KB smem + 64 regs => 4 CTAs/SM (32 warps/SM).
// Grid 592 = 148x4, one wave. Quad CTAs share X rows via L2.
// Warp tile 32x32 (4mg x 2ng), acc 32 regs. All R10/R15 fixes carried:
// coalesced 4-row LDG.128, conflict-free frag swizzles (re-derived for the
// new mapping), B-column permutation + v4 streaming epilogue.
// ============================================================================

#define D_DIM    256
#define N_Q      64
#define M_TILE   128
#define K_CHUNK  32
#define NCHUNKS  8
#define NROWS_T  500000L
#define NTILES_T 3907        // ceil(500000/128)
#define NQUADS   148
#define NCTA     592
#define NTHREADS 256

// smem layout (bytes):
//  B frags [8 nt][16 ksg][32 lane][2 reg] f16x2 = 32768
//  A frags 2 stages x [8 mt][2 ks][4 reg][32 slot] f16x2 = 16384
#define SB_B       0
#define SB_A       32768
#define A_STAGE_B  8192
#define SMEM_TOTAL (SB_A + 2 * A_STAGE_B)   // 49152 -> 4 CTAs/SM

// ---------------------------------------------------------------------------
__device__ __forceinline__ uint32_t smem_u32(const void* p) {
    uint32_t a;
    asm("{ .reg .u64 t; cvta.to.shared.u64 t, %1; cvt.u32.u64 %0, t; }"
        : "=r"(a) : "l"(p));
    return a;
}
__device__ __forceinline__ void sts128(uint32_t a, uint32_t x, uint32_t y,
                                       uint32_t z, uint32_t w) {
    asm volatile("st.shared.v4.b32 [%0], {%1,%2,%3,%4};"
                 :: "r"(a), "r"(x), "r"(y), "r"(z), "r"(w) : "memory");
}
__device__ __forceinline__ void sts32u(uint32_t a, uint32_t v) {
    asm volatile("st.shared.b32 [%0], %1;" :: "r"(a), "r"(v) : "memory");
}
__device__ __forceinline__ void sts16(uint32_t a, uint16_t v) {
    asm volatile("st.shared.u16 [%0], %1;" :: "r"(a), "h"(v) : "memory");
}
__device__ __forceinline__ uint32_t lds32(uint32_t a) {
    uint32_t v;
    asm volatile("ld.shared.b32 %0, [%1];" : "=r"(v) : "r"(a));
    return v;
}
__device__ __forceinline__ uint2 lds64(uint32_t a) {
    uint2 v;
    asm volatile("ld.shared.v2.b32 {%0,%1}, [%2];" : "=r"(v.x), "=r"(v.y) : "r"(a));
    return v;
}
__device__ __forceinline__ void stg128_cs(float* p, float a, float b,
                                          float c, float d) {
    asm volatile("st.global.cs.v4.f32 [%0], {%1,%2,%3,%4};"
                 :: "l"(p), "f"(a), "f"(b), "f"(c), "f"(d) : "memory");
}
__device__ __forceinline__ uint32_t pack_h2(float a, float b) {
    __half2 h = __floats2half2_rn(a, b);     // a -> low, b -> high
    return *reinterpret_cast<uint32_t*>(&h);
}
// D(16x8,f32) += A(16x16,f16,row) * B(16x8,f16,col)
__device__ __forceinline__ void mma_f16(float* c, uint4 a, uint2 b) {
    asm volatile(
        "mma.sync.aligned.m16n8k16.row.col.f32.f16.f16.f32 "
        "{%0,%1,%2,%3}, {%4,%5,%6,%7}, {%8,%9}, {%0,%1,%2,%3};"
        : "+f"(c[0]), "+f"(c[1]), "+f"(c[2]), "+f"(c[3])
        : "r"(a.x), "r"(a.y), "r"(a.z), "r"(a.w), "r"(b.x), "r"(b.y));
}

// ---------------------------------------------------------------------------
// Fused build + persistent GEMM
// ---------------------------------------------------------------------------
__global__ void __launch_bounds__(NTHREADS, 4)
dag_gemm_kernel(const float* __restrict__ X,
                const float* __restrict__ wv,
                const int* __restrict__ rows,
                const int* __restrict__ cols,
                int nnz,
                float* __restrict__ Y) {
    extern __shared__ char smem[];
    const uint32_t sb = smem_u32(smem);
    const int tid  = threadIdx.x;
    const int w    = tid >> 5;
    const int lane = tid & 31;
    const int g    = lane >> 2;      // groupID
    const int tig  = lane & 3;       // thread-in-group
    const int cta  = blockIdx.x;
    const int h    = cta & 3;        // N-quarter (64 cols)
    const int quad = cta >> 2;
    const int ntiles = (NTILES_T - quad + NQUADS - 1) / NQUADS;

    // ---- build B-quarter f16 fragments in smem: zero, then scatter -------
    // B_frag[nt(8)][ksg(16)][lane(32)][breg(2)] f16x2, with column
    // permutation: Y col c within a 32-col warp span sits at frag position
    // p = 2*(c>>3) + (c&1) of ntile (c>>1)&3  => thread tig owns 8
    // contiguous Y columns tig*8..tig*8+7 (v4 epilogue).
    #pragma unroll
    for (int i = 0; i < 8; i++)
        sts128(sb + SB_B + (uint32_t)(tid + (i << 8)) * 16, 0u, 0u, 0u, 0u);
    __syncthreads();
    for (int i = tid; i < nnz; i += NTHREADS) {
        int nl = cols[i] - h * N_Q;
        if ((unsigned)nl < (unsigned)N_Q) {
            int k    = rows[i];
            int ng_  = nl >> 5;
            int c    = nl & 31;
            int p    = ((c >> 3) << 1) + (c & 1);
            int nt   = ng_ * 4 + ((c >> 1) & 3);
            int ksg  = k >> 4,  wi = k & 15;
            int br   = wi >> 3, tg = (wi >> 1) & 3, lo = wi & 1;
            uint32_t a = sb + SB_B
                       + (uint32_t)(((nt * 16 + ksg) * 32 + p * 4 + tg) * 8
                                    + br * 4 + lo * 2);
            __half hv = __float2half_rn(wv[i]);
            sts16(a, *reinterpret_cast<uint16_t*>(&hv));
        }
    }

    // ---- producer mapping: inst i loads rows w*16+i*4+rh (rh=lane>>3),
    //      float4 k4=lane&7 within the 32-k chunk => 4 rows x 128B per inst.
    const int rh = lane >> 3;
    const int k4 = lane & 7;
    const int b2 = (lane >> 2) & 1;    // ks of this thread's data
    const int b1 = (lane >> 1) & 1;    // khalf
    const int b0 = lane & 1;
    const int nchunks = ntiles * NCHUNKS;

    // A-frag STS addresses, layout [mt(8)][ks(2)][reg(4)][slot(32)] f16x2.
    // slot_phys = (4*g + 2*b0 + j) ^ (ks<<4) ^ khalf ; reg = (i>>1)+2*khalf.
    // Bijective; producer sts32 pairs and consumer lds32 both conflict-free.
    uint32_t a_sts[4];
    #pragma unroll
    for (int i = 0; i < 4; i++) {
        int reg  = (i >> 1) + 2 * b1;
        int grow = 4 * (i & 1) + rh;                 // g of this row
        int slot = ((grow * 4 + 2 * b0) ^ (b2 << 4)) ^ b1;
        a_sts[i] = (uint32_t)((((w * 2 + b2) * 4 + reg) * 32 + slot) * 4);
    }

    // warp tiling: 4 m-groups x 2 n-groups, warp tile 32x32
    const int mg = w & 3;
    const int ng = w >> 2;
    float acc[2][4][4];
    #pragma unroll
    for (int mt = 0; mt < 2; mt++)
        #pragma unroll
        for (int nt = 0; nt < 4; nt++)
            #pragma unroll
            for (int q = 0; q < 4; q++) acc[mt][nt][q] = 0.0f;

    __syncthreads();   // B frags ready

    uint2 u[4];
    // ---- prologue: load+convert chunk 0, store to stage 0 ----------------
    {
        long m0 = (long)quad * M_TILE;
        #pragma unroll
        for (int i = 0; i < 4; i++) {
            long grow = m0 + w * 16 + i * 4 + rh;
            float4 v = (grow < NROWS_T)
                ? *reinterpret_cast<const float4*>(X + grow * D_DIM + k4 * 4)
                : make_float4(0.f, 0.f, 0.f, 0.f);
            u[i].x = pack_h2(v.x, v.y);
            u[i].y = pack_h2(v.z, v.w);
        }
        uint32_t ab = sb + SB_A;
        #pragma unroll
        for (int i = 0; i < 4; i++) {
            uint32_t a0 = ab + a_sts[i];
            sts32u(a0, u[i].x);
            sts32u(a0 ^ 4, u[i].y);
        }
    }

    for (int cg = 0; cg < nchunks; cg++) {
        __syncthreads();   // chunk cg resident in stage cg&1

        const int j  = cg >> 3;       // tile
        const int ch = cg & 7;        // 32-k chunk within tile
        const long m0 = (long)(quad + (long)j * NQUADS) * M_TILE;

        // prefetch + convert next chunk into registers (coalesced)
        if (cg + 1 < nchunks) {
            const int jn  = (cg + 1) >> 3;
            const int chn = (cg + 1) & 7;
            long m0n = (long)(quad + (long)jn * NQUADS) * M_TILE;
            #pragma unroll
            for (int i = 0; i < 4; i++) {
                long grow = m0n + w * 16 + i * 4 + rh;
                float4 v = (grow < NROWS_T)
                    ? *reinterpret_cast<const float4*>(
                          X + grow * D_DIM + chn * K_CHUNK + k4 * 4)
                    : make_float4(0.f, 0.f, 0.f, 0.f);
                u[i].x = pack_h2(v.x, v.y);
                u[i].y = pack_h2(v.z, v.w);
            }
        }

        // ---- compute chunk from smem stage -------------------------------
        {
            const uint32_t ab = sb + SB_A + (uint32_t)(cg & 1) * A_STAGE_B;
            const uint32_t bb = sb + SB_B;
            #pragma unroll
            for (int ks = 0; ks < 2; ks++) {
                const int ksg = ch * 2 + ks;
                const uint32_t lx = (uint32_t)((lane ^ (ks << 4)) * 4);
                uint4 a0, a1;
                {
                    uint32_t base0  = ab
                        + (uint32_t)(((mg * 2) * 2 + ks) * 512) + lx;
                    uint32_t base0x = base0 ^ 4;      // khalf bit for regs 2,3
                    a0.x = lds32(base0);
                    a0.y = lds32(base0 + 128);
                    a0.z = lds32(base0x + 256);
                    a0.w = lds32(base0x + 384);
                    uint32_t base1  = base0 + 1024;   // next mt
                    uint32_t base1x = base1 ^ 4;
                    a1.x = lds32(base1);
                    a1.y = lds32(base1 + 128);
                    a1.z = lds32(base1x + 256);
                    a1.w = lds32(base1x + 384);
                }
                uint2 bfr[4];
                #pragma unroll
                for (int nt = 0; nt < 4; nt++)
                    bfr[nt] = lds64(bb + (uint32_t)((((ng * 4 + nt) * 16 + ksg) * 32
                                                    + lane) * 8));
                #pragma unroll
                for (int nt = 0; nt < 4; nt++) {
                    mma_f16(acc[0][nt], a0, bfr[nt]);
                    mma_f16(acc[1][nt], a1, bfr[nt]);
                }
            }
        }

        // ---- store prefetched chunk (keeps barrier path short) -----------
        if (cg + 1 < nchunks) {
            uint32_t ab = sb + SB_A + (uint32_t)((cg + 1) & 1) * A_STAGE_B;
            #pragma unroll
            for (int i = 0; i < 4; i++) {
                uint32_t a0 = ab + a_sts[i];
                sts32u(a0, u[i].x);
                sts32u(a0 ^ 4, u[i].y);
            }
        }

        // ---- epilogue on last chunk of tile (v4, 8 contiguous cols) ------
        if (ch == 7) {
            const long mw = m0 + (long)mg * 32;
            const int  cb = h * N_Q + ng * 32 + tig * 8;
            #pragma unroll
            for (int mt = 0; mt < 2; mt++) {
                long r0 = mw + mt * 16 + g;
                long r1 = r0 + 8;
                if (r0 < NROWS_T) {
                    float* d0 = Y + r0 * D_DIM + cb;
                    stg128_cs(d0,     acc[mt][0][0], acc[mt][0][1],
                                      acc[mt][1][0], acc[mt][1][1]);
                    stg128_cs(d0 + 4, acc[mt][2][0], acc[mt][2][1],
                                      acc[mt][3][0], acc[mt][3][1]);
                }
                if (r1 < NROWS_T) {
                    float* d1 = Y + r1 * D_DIM + cb;
                    stg128_cs(d1,     acc[mt][0][2], acc[mt][0][3],
                                      acc[mt][1][2], acc[mt][1][3]);
                    stg128_cs(d1 + 4, acc[mt][2][2], acc[mt][2][3],
                                      acc[mt][3][2], acc[mt][3][3]);
                }
                #pragma unroll
                for (int nt = 0; nt < 4; nt++)
                    #pragma unroll
                    for (int q = 0; q < 4; q++) acc[mt][nt][q] = 0.0f;
            }
        }
    }
}

// ---------------------------------------------------------------------------
extern "C" void kernel_launch(void* const* d_in, const int* in_sizes, int n_in,
                              void* d_out, int out_size) {
    const float* X    = (const float*)d_in[0];
    const float* wv   = (const float*)d_in[1];
    const int*   rows = (const int*)d_in[2];
    const int*   cols = (const int*)d_in[3];
    const int nnz = in_sizes[1];

    cudaFuncSetAttribute(dag_gemm_kernel,
                         cudaFuncAttributeMaxDynamicSharedMemorySize, SMEM_TOTAL);
    dag_gemm_kernel<<<NCTA, NTHREADS, SMEM_TOTAL>>>(X, wv, rows, cols, nnz,
                                                    (float*)d_out);
}